// round 8
// baseline (speedup 1.0000x reference)
#include <cuda_runtime.h>

// DEMA over x[B=32, T=4096, C=512], scan along T.
//   s_t = a*x_t + (1-a)*(s_{t-1} + b_{t-1})
//   b_t = a*B*x_t - a*B*s_{t-1} + (1-a*B)*b_{t-1}
// Time-chunked with warm-up halo (spectral radius sqrt(0.7)=0.8367;
// HALO=64 -> state error ~1e-5, threshold 1e-3).
//
// Verified structure (protect):
//  - CHUNK=256/HALO=64: 63 MB halo, fits L2 for retention.
//  - halo loads DEFAULT policy -> retained in L2; neighbor's body-tail reads
//    hit (measured: DRAM traffic 518 MB ~= floor).
//  - body loads __ldcs, stores __stcs (single-use streaming).
// New in R8: float1 lanes, 512 thr/block -> 8192 warps (occ 40%->~75%) to
// push achieved HBM BW past the latency-limited ~5.9 TB/s.

#define B_DIM 32
#define T_DIM 4096
#define C_DIM 512
#define CHUNK 256
#define HALO  64
#define NCHUNK (T_DIM / CHUNK)   // 16
#define THREADS 512              // 1 channel per thread
#define PF 8                     // prefetch depth

#define ALPHA 0.3f
#define BETA  0.1f

__device__ __forceinline__ void dema_step(float& s, float& g, const float xv) {
    const float OMA  = 1.0f - ALPHA;           // 0.7
    const float AB   = ALPHA * BETA;           // 0.03
    const float OMAB = 1.0f - ALPHA * BETA;    // 0.97
    float ax   = ALPHA * xv;                   // off critical path
    float t1   = fmaf(AB, xv, OMAB * g);       // b-chain
    float snew = fmaf(OMA, s + g, ax);         // s-chain
    float gnew = fmaf(-AB, s, t1);
    s = snew;
    g = gnew;
}

__global__ __launch_bounds__(THREADS, 3)
void dema_kernel(const float* __restrict__ x, float* __restrict__ out) {
    const int bid = blockIdx.x;
    const int ci  = bid % NCHUNK;          // time chunk
    const int b   = bid / NCHUNK;          // batch
    const int c   = threadIdx.x;           // channel

    const size_t base = (size_t)b * T_DIM * C_DIM + c;
    const float* __restrict__ xp = x + base;
    float* __restrict__       op = out + base;
    const int S = C_DIM;                   // stride per time step

    const int t0    = ci * CHUNK;
    const int tend  = t0 + CHUNK;
    const int tinit = (ci == 0) ? 0 : (t0 - HALO);

    // init state from x[tinit], x[tinit+1] (halo region: cached loads)
    float v0 = xp[(size_t)tinit * S];
    float v1 = xp[(size_t)(tinit + 1) * S];
    float s = v0;
    float g = v1 - v0;
    if (ci == 0) op[0] = v0;               // out[0] = s0 = x[0] (exact)

    int t = tinit + 1;                     // first step to compute

    // prefetch window: xv[k] = x[t+k] (still halo region -> cached)
    float xv[PF];
    xv[0] = v1;
#pragma unroll
    for (int k = 1; k < PF; k++) xv[k] = xp[(size_t)(t + k) * S];

    // Phase A: warm-up iterations whose LOADS (t+PF..t+2PF-1) are all < t0.
    // Default (cached) loads: these halo lines stay in L2 for the
    // neighboring block's body-tail reads. No stores here.
    for (; t + 2 * PF - 1 < t0; t += PF) {
        float xn[PF];
#pragma unroll
        for (int k = 0; k < PF; k++)
            xn[k] = xp[(size_t)(t + PF + k) * S];
#pragma unroll
        for (int k = 0; k < PF; k++) {
            dema_step(s, g, xv[k]);
            xv[k] = xn[k];
        }
    }

    // Phase B: remaining warm-up + body. Streaming loads (__ldcs), streaming
    // stores (__stcs), store predicated on t+k >= t0.
    for (; t + PF - 1 < tend; t += PF) {
        float xn[PF];
#pragma unroll
        for (int k = 0; k < PF; k++) {
            int tn = t + PF + k;
            tn = (tn >= T_DIM) ? (T_DIM - 1) : tn;   // clamp at sequence end
            xn[k] = __ldcs(&xp[(size_t)tn * S]);
        }
#pragma unroll
        for (int k = 0; k < PF; k++) {
            dema_step(s, g, xv[k]);
            if (t + k >= t0)
                __stcs(&op[(size_t)(t + k) * S], s);
            xv[k] = xn[k];
        }
    }

    // epilogue (<= PF-1 steps); xv[k] already holds x[t..]
#pragma unroll
    for (int k = 0; k < PF - 1 && t < tend; t++, k++) {
        dema_step(s, g, xv[k]);
        __stcs(&op[(size_t)t * S], s);
    }
}

extern "C" void kernel_launch(void* const* d_in, const int* in_sizes, int n_in,
                              void* d_out, int out_size) {
    const float* x = (const float*)d_in[0];
    float* out = (float*)d_out;
    dim3 grid(B_DIM * NCHUNK);   // 512 blocks x 16 warps = 8192 warps
    dim3 block(THREADS);
    dema_kernel<<<grid, block>>>(x, out);
}

// round 12
// speedup vs baseline: 1.2676x; 1.2676x over previous
#include <cuda_runtime.h>

// DEMA over x[B=32, T=4096, C=512], scan along T.
//   s_t = a*x_t + (1-a)*(s_{t-1} + b_{t-1})
//   b_t = a*B*x_t - a*B*s_{t-1} + (1-a*B)*b_{t-1}
// Time-chunked with warm-up halo (spectral radius sqrt(0.7)=0.8367;
// HALO=64 -> state error ~1e-5, threshold 1e-3).
//
// Verified config (protect): float2 lanes @ 4096 warps total = 6.0-6.2 TB/s
// (float4 -> 5.5, float1 -> 4.7: R8 regression). CHUNK=256/HALO=64 with
// cached halo loads -> L2 retention, measured DRAM traffic 518 MB ~= floor.
// R9 change: split each (b,chunk) into 2 blocks of 128 thr -> grid=1024,
// 6.92 blocks/SM (vs 3.46) to kill the last-wave imbalance tail.

#define B_DIM 32
#define T_DIM 4096
#define C_DIM 512
#define CHUNK 256
#define HALO  64
#define NCHUNK (T_DIM / CHUNK)   // 16
#define THREADS 128              // float2 lanes: 128*2 = 256 channels/block
#define CSPLIT 2                 // blocks per (batch, chunk)
#define PF 8                     // prefetch depth

#define ALPHA 0.3f
#define BETA  0.1f

__device__ __forceinline__ void dema_step(float (&s)[2], float (&g)[2], const float2 xv) {
    const float OMA  = 1.0f - ALPHA;           // 0.7
    const float AB   = ALPHA * BETA;           // 0.03
    const float OMAB = 1.0f - ALPHA * BETA;    // 0.97
    float xs[2] = {xv.x, xv.y};
#pragma unroll
    for (int i = 0; i < 2; i++) {
        float ax   = ALPHA * xs[i];                 // off critical path
        float t1   = fmaf(AB, xs[i], OMAB * g[i]);  // b-chain
        float snew = fmaf(OMA, s[i] + g[i], ax);    // s-chain
        float gnew = fmaf(-AB, s[i], t1);
        s[i] = snew;
        g[i] = gnew;
    }
}

__global__ __launch_bounds__(THREADS, 8)
void dema_kernel(const float* __restrict__ x, float* __restrict__ out) {
    const int bid   = blockIdx.x;
    const int half  = bid % CSPLIT;               // channel half
    const int ci    = (bid / CSPLIT) % NCHUNK;    // time chunk
    const int b     = bid / (CSPLIT * NCHUNK);    // batch
    const int c2    = half * THREADS + threadIdx.x;  // float2 lane in [0,256)

    const size_t base = (size_t)b * T_DIM * C_DIM + 2 * c2;
    const float2* __restrict__ xp = (const float2*)(x + base);
    float2* __restrict__       op = (float2*)(out + base);
    const int S = C_DIM / 2;               // 256 float2 per time step

    const int t0    = ci * CHUNK;
    const int tend  = t0 + CHUNK;
    const int tinit = (ci == 0) ? 0 : (t0 - HALO);

    // init state from x[tinit], x[tinit+1] (halo region: cached loads)
    float2 v0 = xp[(size_t)tinit * S];
    float2 v1 = xp[(size_t)(tinit + 1) * S];
    float s[2] = {v0.x, v0.y};
    float g[2] = {v1.x - v0.x, v1.y - v0.y};
    if (ci == 0) op[0] = v0;               // out[0] = s0 = x[0] (exact)

    int t = tinit + 1;                     // first step to compute

    // prefetch window: xv[k] = x[t+k] (still halo region -> cached)
    float2 xv[PF];
    xv[0] = v1;
#pragma unroll
    for (int k = 1; k < PF; k++) xv[k] = xp[(size_t)(t + k) * S];

    // Phase A: warm-up iterations whose LOADS (t+PF..t+2PF-1) are all < t0.
    // Default (cached) loads: these halo lines stay in L2 for the
    // neighboring block's body-tail reads. No stores here.
    for (; t + 2 * PF - 1 < t0; t += PF) {
        float2 xn[PF];
#pragma unroll
        for (int k = 0; k < PF; k++)
            xn[k] = xp[(size_t)(t + PF + k) * S];
#pragma unroll
        for (int k = 0; k < PF; k++) {
            dema_step(s, g, xv[k]);
            xv[k] = xn[k];
        }
    }

    // Phase B: remaining warm-up + body. Streaming loads (__ldcs), streaming
    // stores (__stcs), store predicated on t+k >= t0.
    for (; t + PF - 1 < tend; t += PF) {
        float2 xn[PF];
#pragma unroll
        for (int k = 0; k < PF; k++) {
            int tn = t + PF + k;
            tn = (tn >= T_DIM) ? (T_DIM - 1) : tn;   // clamp at sequence end
            xn[k] = __ldcs(&xp[(size_t)tn * S]);
        }
#pragma unroll
        for (int k = 0; k < PF; k++) {
            dema_step(s, g, xv[k]);
            if (t + k >= t0)
                __stcs(&op[(size_t)(t + k) * S], make_float2(s[0], s[1]));
            xv[k] = xn[k];
        }
    }

    // epilogue (<= PF-1 steps); xv[k] already holds x[t..]
#pragma unroll
    for (int k = 0; k < PF - 1 && t < tend; t++, k++) {
        dema_step(s, g, xv[k]);
        __stcs(&op[(size_t)t * S], make_float2(s[0], s[1]));
    }
}

extern "C" void kernel_launch(void* const* d_in, const int* in_sizes, int n_in,
                              void* d_out, int out_size) {
    const float* x = (const float*)d_in[0];
    float* out = (float*)d_out;
    dim3 grid(B_DIM * NCHUNK * CSPLIT);   // 1024 blocks x 4 warps = 4096 warps
    dim3 block(THREADS);
    dema_kernel<<<grid, block>>>(x, out);
}